// round 9
// baseline (speedup 1.0000x reference)
#include <cuda_runtime.h>
#include <cuda_fp16.h>

// ---------------------------------------------------------------------------
// weighted_loss over B=4.2M rows x 3 tasks. Persistent single-wave grid,
// now 8 CTAs/SM: 2-row groups loaded as float2 (14 data regs vs 28 for the
// old float4 4-row groups) so the kernel fits 32 regs -> 2048 threads/SM.
// Compute path: half2 AIS counting, ex2.approx for 1.1^n, saturate-identity
// wmid, 3-FMA exp tail. Single launch, threadfence reduction.
// ---------------------------------------------------------------------------

#define MAX_BLOCKS 2048

__device__ float g_partial[MAX_BLOCKS];
__device__ unsigned int g_ticket = 0;   // returns to 0 each call -> deterministic

__device__ __forceinline__ __half2 h2c(unsigned short u) {
    __half2_raw r; r.x = u; r.y = u;
    return *reinterpret_cast<__half2*>(&r);
}

__device__ __forceinline__ float ex2_approx(float x) {
    float r;
    asm("ex2.approx.f32 %0, %1;" : "=f"(r) : "f"(x));
    return r;
}

__device__ __forceinline__ float rcp_approx(float x) {
    float r;
    asm("rcp.approx.f32 %0, %1;" : "=f"(r) : "f"(x));
    return r;
}

// exp(u) for u in [-0.23, 0.7], degree-3 Horner. abs err < 1e-4 on range.
__device__ __forceinline__ float exp3(float u) {
    float h = fmaf(u, 0.16666667f, 0.5f);
    h = fmaf(u, h, 1.0f);
    return fmaf(u, h, 1.0f);
}

// w_cls = 1.1^|ais(p)-ais(t)|, (p,t) packed in half2 vs 5 broadcast thresholds
__device__ __forceinline__ float wcls5(__half2 pt, __half2 a0, __half2 a1,
                                       __half2 a2, __half2 a3, __half2 a4) {
    __half2 acc = __hge2(pt, a0);
    acc = __hadd2(acc, __hge2(pt, a1));
    acc = __hadd2(acc, __hge2(pt, a2));
    acc = __hadd2(acc, __hge2(pt, a3));
    acc = __hadd2(acc, __hge2(pt, a4));
    float2 f = __half22float2(acc);
    float d = fabsf(f.x - f.y);
    return ex2_approx(d * 0.13750352f);   // log2(1.1)
}

// w_mid = 1 + piecewise(yt) [+1 if yp<0], via saturate identity.
// nb = -b/(c-b); neg_k = -ln2/d (so -k*(yt-d) = ln2 + neg_k*yt).
__device__ __forceinline__ float wmid_f(float yt, float yp,
                                        float d, float inv_a,
                                        float inv_cb, float nb, float neg_k) {
    float s1 = __saturatef(yt * inv_a);
    float s2 = __saturatef(fmaf(yt, inv_cb, nb));
    float w  = (1.0f - s2) + s1;
    float e  = exp3(fmaf(neg_k, yt, 0.69314718f));
    w = (yt > d) ? e : w;
    w += (yp < 0.0f) ? 1.0f : 0.0f;
    return w;
}

__device__ __forceinline__ float row_loss(float ph, float pd, float pn,
                                          float th, float td, float tn,
                                          int o) {
    // ---- head: thr {150,500,1000,1800,2600} (fp16-exact)
    float wch = wcls5(__floats2half2_rn(ph, th),
                      h2c(0x58B0), h2c(0x5FD0), h2c(0x63D0),
                      h2c(0x6708), h2c(0x6914));
    float mh = wmid_f(th, ph, 2000.0f, 0.0125f, 0.004f, -6.0f, -3.4657359e-4f);
    float L = fabsf(ph - th) * wch * mh;

    // ---- chest: thr {22,35,45,55,65}*s  <=>  (x/s) vs thr
    float s = fmaf(0.1f, (float)o, 0.8f);
    float is = rcp_approx(s);
    __half2 is2 = __half2half2(__float2half_rn(is));
    float wcc = wcls5(__hmul2(__floats2half2_rn(pd, td), is2),
                      h2c(0x4D80), h2c(0x5060), h2c(0x51A0),
                      h2c(0x52E0), h2c(0x5410));
    float mc = wmid_f(td, pd, 100.0f, 0.1f, 0.1f, -7.5f, -6.9314718e-3f);
    L += fabsf(pd - td) * wcc * mc;

    // ---- neck: thr {0.2,0.5,1.0,1.5,2.0}
    float wcn = wcls5(__floats2half2_rn(pn, tn),
                      h2c(0x3266), h2c(0x3800), h2c(0x3C00),
                      h2c(0x3E00), h2c(0x4000));
    float mn = wmid_f(tn, pn, 1.9f, 6.6666667f, 5.0f, -7.5f, -0.36481431f);
    L += fabsf(pn - tn) * wcn * mn;

    return L;
}

__global__ void __launch_bounds__(256, 8)
loss_kernel(const float* __restrict__ pred,
            const float* __restrict__ tru,
            const int* __restrict__ ot,
            int ngroups, int nrows,
            float* __restrict__ out, float invN) {
    __shared__ float warpsum[8];
    __shared__ int s_islast;

    const float2* __restrict__ pv = (const float2*)pred;
    const float2* __restrict__ tv = (const float2*)tru;
    const int2* __restrict__ ov = (const int2*)ot;

    int tid = blockIdx.x * blockDim.x + threadIdx.x;
    int stride = gridDim.x * blockDim.x;

    float acc = 0.0f;
    #pragma unroll 1
    for (int g = tid; g < ngroups; g += stride) {
        float2 p0 = pv[3 * g + 0];
        float2 p1 = pv[3 * g + 1];
        float2 p2 = pv[3 * g + 2];
        float2 t0 = tv[3 * g + 0];
        float2 t1 = tv[3 * g + 1];
        float2 t2 = tv[3 * g + 2];
        int2 o = ov[g];
        acc += row_loss(p0.x, p0.y, p1.x, t0.x, t0.y, t1.x, o.x);
        acc += row_loss(p1.y, p2.x, p2.y, t1.y, t2.x, t2.y, o.y);
    }
    // tail rows (B % 2 != 0 -- not hit for B=4194304)
    for (int r = 2 * ngroups + tid; r < nrows; r += stride) {
        acc += row_loss(pred[3 * r + 0], pred[3 * r + 1], pred[3 * r + 2],
                        tru[3 * r + 0], tru[3 * r + 1], tru[3 * r + 2], ot[r]);
    }

    // ---- block reduce (float) ----
    #pragma unroll
    for (int off = 16; off > 0; off >>= 1)
        acc += __shfl_xor_sync(0xffffffffu, acc, off);

    int lane = threadIdx.x & 31;
    int warp = threadIdx.x >> 5;
    if (lane == 0) warpsum[warp] = acc;
    __syncthreads();

    if (threadIdx.x == 0) {
        float bsum = 0.0f;
        #pragma unroll
        for (int w = 0; w < 8; w++) bsum += warpsum[w];
        g_partial[blockIdx.x] = bsum;
        __threadfence();
        unsigned int v = atomicAdd(&g_ticket, 1u);
        s_islast = (v == gridDim.x - 1) ? 1 : 0;
    }
    __syncthreads();

    // ---- last block reduces all partials ----
    if (s_islast) {
        float d = 0.0f;
        for (int i = threadIdx.x; i < gridDim.x; i += blockDim.x)
            d += __ldcg(&g_partial[i]);
        #pragma unroll
        for (int off = 16; off > 0; off >>= 1)
            d += __shfl_xor_sync(0xffffffffu, d, off);
        if (lane == 0) warpsum[warp] = d;
        __syncthreads();
        if (threadIdx.x == 0) {
            float tot = 0.0f;
            #pragma unroll
            for (int w = 0; w < 8; w++) tot += warpsum[w];
            out[0] = tot * invN;
            g_ticket = 0;   // reset for next graph replay
        }
    }
}

extern "C" void kernel_launch(void* const* d_in, const int* in_sizes, int n_in,
                              void* d_out, int out_size) {
    const float* pred = (const float*)d_in[0];
    const float* tru  = (const float*)d_in[1];
    const int*   ot   = (const int*)d_in[2];
    float* out = (float*)d_out;

    int B = in_sizes[0] / 3;
    int ngroups = B / 2;

    // Persistent single wave: 152 SMs x 8 CTAs/SM
    int threads = 256;
    int blocks = 1216;
    int maxb = (ngroups + threads - 1) / threads;
    if (blocks > maxb) blocks = maxb;
    if (blocks < 1) blocks = 1;
    if (blocks > MAX_BLOCKS) blocks = MAX_BLOCKS;

    loss_kernel<<<blocks, threads>>>(pred, tru, ot, ngroups, B, out,
                                     1.0f / (float)B);
}

// round 13
// speedup vs baseline: 1.0102x; 1.0102x over previous
#include <cuda_runtime.h>
#include <cuda_fp16.h>

// ---------------------------------------------------------------------------
// weighted_loss over B=4.2M rows x 3 tasks. Persistent single-wave grid,
// 2-row groups (float2 loads). Weight math fully packed in half2 across the
// row pair: AIS counts (HSET2/HADD2), |dAIS| via PRMT+HSUB2, 1.1^d via
// ex2.approx.f16x2 (one MUFU per pair), w_mid via HFMA2.SAT saturate identity
// + HGT2 mask select, merged product in half. Base |p-t| and accumulation in
// fp32. Single launch, threadfence reduction.
// ---------------------------------------------------------------------------

#define MAX_BLOCKS 2048

__device__ float g_partial[MAX_BLOCKS];
__device__ unsigned int g_ticket = 0;   // returns to 0 each call -> deterministic

__device__ __forceinline__ __half2 h2c(unsigned short u) {
    __half2_raw r; r.x = u; r.y = u;
    return *reinterpret_cast<__half2*>(&r);
}
__device__ __forceinline__ unsigned int h2u(__half2 h) {
    return *reinterpret_cast<unsigned int*>(&h);
}
__device__ __forceinline__ __half2 u2h(unsigned int u) {
    return *reinterpret_cast<__half2*>(&u);
}
__device__ __forceinline__ __half2 h2ex2(__half2 x) {
    unsigned int ri, xi = h2u(x);
    asm("ex2.approx.f16x2 %0, %1;" : "=r"(ri) : "r"(xi));
    return u2h(ri);
}
__device__ __forceinline__ float rcp_approx(float x) {
    float r; asm("rcp.approx.f32 %0, %1;" : "=f"(r) : "f"(x)); return r;
}

// per-lane count of thresholds passed: lanes (p, t) of one row
__device__ __forceinline__ __half2 counts5(__half2 v, __half2 a0, __half2 a1,
                                           __half2 a2, __half2 a3, __half2 a4) {
    __half2 acc = __hge2(v, a0);
    acc = __hadd2(acc, __hge2(v, a1));
    acc = __hadd2(acc, __hge2(v, a2));
    acc = __hadd2(acc, __hge2(v, a3));
    acc = __hadd2(acc, __hge2(v, a4));
    return acc;
}

// packed w_cls = 1.1^|dAIS| for two rows from their (cnt_p, cnt_t) half2s
__device__ __forceinline__ __half2 wcls2(__half2 c0, __half2 c1) {
    unsigned int lo = __byte_perm(h2u(c0), h2u(c1), 0x5410); // (cnt_p0, cnt_p1)
    unsigned int hi = __byte_perm(h2u(c0), h2u(c1), 0x7632); // (cnt_t0, cnt_t1)
    __half2 dd = __habs2(__hsub2(u2h(lo), u2h(hi)));
    return h2ex2(__hmul2(dd, h2c(0x3066)));   // 2^(log2(1.1)*d)
}

// packed w_mid for two rows: t2 = (t0,t1), p2 = (p0,p1)
// w = 1 + sat(t*ca) - sat(t*ccb + cnb) for t<=d; exp(ln2 + ck*t) for t>d;
// +1 where p<0. All boundaries continuous -> fp16 compares safe.
__device__ __forceinline__ __half2 wmid2(__half2 t2, __half2 p2,
                                         __half2 ca, __half2 ccb, __half2 cnb,
                                         __half2 cd, __half2 ck) {
    const __half2 one = h2c(0x3C00);
    __half2 s1 = __hfma2_sat(t2, ca, h2c(0x0000));
    __half2 s2 = __hfma2_sat(t2, ccb, cnb);
    __half2 w  = __hadd2(__hsub2(one, s2), s1);
    __half2 u  = __hfma2(ck, t2, h2c(0x398C));       // ln2 + (-k)*t  in [-0.23,0.7]
    __half2 h  = __hfma2(u, h2c(0x3155), h2c(0x3800)); // 1/6, 1/2
    h = __hfma2(u, h, one);
    __half2 e  = __hfma2(u, h, one);                 // exp3(u)
    __half2 md = __hgt2(t2, cd);                     // 1.0 where t > d
    w = __hfma2(__hsub2(e, w), md, w);               // select exp tail
    w = __hadd2(w, __hlt2(p2, h2c(0x0000)));         // +1 where p < 0
    return w;
}

// one task for a pair of rows. v* = packed (p,t) used for AIS compare
// (possibly pre-scaled, chest); vr* = raw packed (p,t) for w_mid.
__device__ __forceinline__ float task_pair(
    float p0, float t0, float p1, float t1,
    __half2 v0, __half2 v1, __half2 vr0, __half2 vr1,
    __half2 a0, __half2 a1, __half2 a2, __half2 a3, __half2 a4,
    __half2 ca, __half2 ccb, __half2 cnb, __half2 cd, __half2 ck) {
    __half2 c0 = counts5(v0, a0, a1, a2, a3, a4);
    __half2 c1 = counts5(v1, a0, a1, a2, a3, a4);
    __half2 wc = wcls2(c0, c1);
    __half2 t2 = u2h(__byte_perm(h2u(vr0), h2u(vr1), 0x7632)); // (t0, t1)
    __half2 p2 = u2h(__byte_perm(h2u(vr0), h2u(vr1), 0x5410)); // (p0, p1)
    __half2 w  = __hmul2(wc, wmid2(t2, p2, ca, ccb, cnb, cd, ck));
    float2 wf = __half22float2(w);
    return fabsf(p0 - t0) * wf.x + fabsf(p1 - t1) * wf.y;
}

__device__ __forceinline__ float pair_loss(
    float ph0, float pd0, float pn0, float th0, float td0, float tn0, int o0,
    float ph1, float pd1, float pn1, float th1, float td1, float tn1, int o1) {
    // ---- head: thr {150,500,1000,1800,2600}; a=80 b=1500 c=1750 d=2000
    __half2 vh0 = __floats2half2_rn(ph0, th0);
    __half2 vh1 = __floats2half2_rn(ph1, th1);
    float L = task_pair(ph0, th0, ph1, th1, vh0, vh1, vh0, vh1,
        h2c(0x58B0), h2c(0x5FD0), h2c(0x63D0), h2c(0x6708), h2c(0x6914),
        h2c(0x2266),   // 1/80
        h2c(0x1C19),   // 1/250
        h2c(0xC600),   // -6
        h2c(0x67D0),   // 2000
        h2c(0x8DAE));  // -ln2/2000

    // ---- chest: thr {22,35,45,55,65}*s; compare x*(1/s) vs thr; a=10 b=75 c=85 d=100
    float s0 = fmaf(0.1f, (float)o0, 0.8f);
    float s1f = fmaf(0.1f, (float)o1, 0.8f);
    __half2 is0 = __half2half2(__float2half_rn(rcp_approx(s0)));
    __half2 is1 = __half2half2(__float2half_rn(rcp_approx(s1f)));
    __half2 vrc0 = __floats2half2_rn(pd0, td0);
    __half2 vrc1 = __floats2half2_rn(pd1, td1);
    __half2 vc0 = __hmul2(vrc0, is0);
    __half2 vc1 = __hmul2(vrc1, is1);
    L += task_pair(pd0, td0, pd1, td1, vc0, vc1, vrc0, vrc1,
        h2c(0x4D80), h2c(0x5060), h2c(0x51A0), h2c(0x52E0), h2c(0x5410),
        h2c(0x2E66),   // 1/10
        h2c(0x2E66),   // 1/10
        h2c(0xC780),   // -7.5
        h2c(0x5640),   // 100
        h2c(0x9F19));  // -ln2/100

    // ---- neck: thr {0.2,0.5,1.0,1.5,2.0}; a=0.15 b=1.5 c=1.7 d=1.9
    __half2 vn0 = __floats2half2_rn(pn0, tn0);
    __half2 vn1 = __floats2half2_rn(pn1, tn1);
    L += task_pair(pn0, tn0, pn1, tn1, vn0, vn1, vn0, vn1,
        h2c(0x3266), h2c(0x3800), h2c(0x3C00), h2c(0x3E00), h2c(0x4000),
        h2c(0x46AB),   // 1/0.15
        h2c(0x4500),   // 5
        h2c(0xC780),   // -7.5
        h2c(0x3F9A),   // 1.9
        h2c(0xB5D6));  // -ln2/1.9

    return L;
}

__global__ void __launch_bounds__(256, 6)
loss_kernel(const float* __restrict__ pred,
            const float* __restrict__ tru,
            const int* __restrict__ ot,
            int ngroups, int nrows,
            float* __restrict__ out, float invN) {
    __shared__ float warpsum[8];
    __shared__ int s_islast;

    const float2* __restrict__ pv = (const float2*)pred;
    const float2* __restrict__ tv = (const float2*)tru;
    const int2* __restrict__ ov = (const int2*)ot;

    int tid = blockIdx.x * blockDim.x + threadIdx.x;
    int stride = gridDim.x * blockDim.x;

    float acc = 0.0f;
    #pragma unroll 1
    for (int g = tid; g < ngroups; g += stride) {
        float2 p0 = pv[3 * g + 0];
        float2 p1 = pv[3 * g + 1];
        float2 p2 = pv[3 * g + 2];
        float2 t0 = tv[3 * g + 0];
        float2 t1 = tv[3 * g + 1];
        float2 t2 = tv[3 * g + 2];
        int2 o = ov[g];
        acc += pair_loss(p0.x, p0.y, p1.x, t0.x, t0.y, t1.x, o.x,
                         p1.y, p2.x, p2.y, t1.y, t2.x, t2.y, o.y);
    }
    // tail rows (B % 2 != 0 -- not hit for B=4194304); second row zeroed
    for (int r = 2 * ngroups + tid; r < nrows; r += stride) {
        acc += pair_loss(pred[3 * r + 0], pred[3 * r + 1], pred[3 * r + 2],
                         tru[3 * r + 0], tru[3 * r + 1], tru[3 * r + 2], ot[r],
                         0.0f, 0.0f, 0.0f, 0.0f, 0.0f, 0.0f, 0);
    }

    // ---- block reduce (float) ----
    #pragma unroll
    for (int off = 16; off > 0; off >>= 1)
        acc += __shfl_xor_sync(0xffffffffu, acc, off);

    int lane = threadIdx.x & 31;
    int warp = threadIdx.x >> 5;
    if (lane == 0) warpsum[warp] = acc;
    __syncthreads();

    if (threadIdx.x == 0) {
        float bsum = 0.0f;
        #pragma unroll
        for (int w = 0; w < 8; w++) bsum += warpsum[w];
        g_partial[blockIdx.x] = bsum;
        __threadfence();
        unsigned int v = atomicAdd(&g_ticket, 1u);
        s_islast = (v == gridDim.x - 1) ? 1 : 0;
    }
    __syncthreads();

    // ---- last block reduces all partials ----
    if (s_islast) {
        float d = 0.0f;
        for (int i = threadIdx.x; i < gridDim.x; i += blockDim.x)
            d += __ldcg(&g_partial[i]);
        #pragma unroll
        for (int off = 16; off > 0; off >>= 1)
            d += __shfl_xor_sync(0xffffffffu, d, off);
        if (lane == 0) warpsum[warp] = d;
        __syncthreads();
        if (threadIdx.x == 0) {
            float tot = 0.0f;
            #pragma unroll
            for (int w = 0; w < 8; w++) tot += warpsum[w];
            out[0] = tot * invN;
            g_ticket = 0;   // reset for next graph replay
        }
    }
}

extern "C" void kernel_launch(void* const* d_in, const int* in_sizes, int n_in,
                              void* d_out, int out_size) {
    const float* pred = (const float*)d_in[0];
    const float* tru  = (const float*)d_in[1];
    const int*   ot   = (const int*)d_in[2];
    float* out = (float*)d_out;

    int B = in_sizes[0] / 3;
    int ngroups = B / 2;

    // Persistent single wave: 152 SMs x 6 CTAs/SM
    int threads = 256;
    int blocks = 912;
    int maxb = (ngroups + threads - 1) / threads;
    if (blocks > maxb) blocks = maxb;
    if (blocks < 1) blocks = 1;
    if (blocks > MAX_BLOCKS) blocks = MAX_BLOCKS;

    loss_kernel<<<blocks, threads>>>(pred, tru, ot, ngroups, B, out,
                                     1.0f / (float)B);
}